// round 5
// baseline (speedup 1.0000x reference)
#include <cuda_runtime.h>
#include <cstdint>

#define NB    16
#define LSEQ  2048
#define DDIM  1024

#define BM 128
#define BN 256
#define BK 16
#define LDA 20      // floats; conflict-free LDSM rows
#define LDV 264     // floats; 264%32==8 -> conflict-free scalar B LDS

// stage sizes in floats
#define A_FL (BM * LDA)          // 2560
#define B_FL (BN * LDA)          // 5120
#define V_FL (BK * LDV)          // 4224
#define QK_SMEM_BYTES ((2 * A_FL + 2 * B_FL) * 4)   // 61440
#define PV_SMEM_BYTES ((2 * A_FL + 2 * V_FL) * 4)   // 54272

// 256 MB scratch for scores/probs: S[b, q, k]
__device__ float g_S[(size_t)NB * LSEQ * LSEQ];

__device__ __forceinline__ float to_tf32(float x) {
    float r;
    asm("cvt.rna.tf32.f32 %0, %1;" : "=f"(r) : "f"(x));
    return r;
}
__device__ __forceinline__ float4 to_tf32_4(float4 v) {
    v.x = to_tf32(v.x); v.y = to_tf32(v.y); v.z = to_tf32(v.z); v.w = to_tf32(v.w);
    return v;
}
__device__ __forceinline__ uint32_t sptr(const void* p) {
    return (uint32_t)__cvta_generic_to_shared(p);
}
__device__ __forceinline__ void ldsm4(uint32_t r[4], uint32_t a) {
    asm volatile("ldmatrix.sync.aligned.m8n8.x4.shared.b16 {%0,%1,%2,%3}, [%4];"
                 : "=r"(r[0]), "=r"(r[1]), "=r"(r[2]), "=r"(r[3]) : "r"(a));
}
__device__ __forceinline__ void mma8(float c[4], const uint32_t a[4],
                                     uint32_t b0, uint32_t b1) {
    asm volatile("mma.sync.aligned.m16n8k8.row.col.f32.tf32.tf32.f32 "
                 "{%0,%1,%2,%3}, {%4,%5,%6,%7}, {%8,%9}, {%0,%1,%2,%3};"
                 : "+f"(c[0]), "+f"(c[1]), "+f"(c[2]), "+f"(c[3])
                 : "r"(a[0]), "r"(a[1]), "r"(a[2]), "r"(a[3]), "r"(b0), "r"(b1));
}

// ---------------------------------------------------------------------------
// Kernel 1: S = Q @ K^T, 128x256 block, 64x64 warp tiles, double-buffered
// ---------------------------------------------------------------------------
__global__ __launch_bounds__(256, 1) void qk_kernel(const float* __restrict__ Q,
                                                    const float* __restrict__ Kin) {
    const int n0 = blockIdx.x * BN;
    const int m0 = blockIdx.y * BM;
    const int b  = blockIdx.z;
    if (n0 > m0 + BM - 1) return;     // fully masked tile

    extern __shared__ float smf[];
    float* As = smf;                  // 2 stages of A_FL
    float* Bs = smf + 2 * A_FL;       // 2 stages of B_FL

    const float* Qb = Q   + (size_t)b * LSEQ * DDIM;
    const float* Kb = Kin + (size_t)b * LSEQ * DDIM;
    float*       Sb = g_S + (size_t)b * LSEQ * LSEQ;

    const int tid = threadIdx.x, lane = tid & 31, wid = tid >> 5;
    const int wm = (wid & 1) * 64, wn = (wid >> 1) * 64;

    // gmem load coords
    const int arow = tid >> 2, ach = (tid & 3) * 4;   // A: rows arow, arow+64

    // LDSM lane addressing
    const int a_r = lane & 15, a_c = (lane & 16) >> 2;
    const int b_r = (lane & 7) + ((lane & 16) >> 1), b_c = (lane & 8) >> 1;

    uint32_t a_addr[4], b_addr[4];
#pragma unroll
    for (int h = 0; h < 4; h++) {
        a_addr[h] = sptr(&As[(wm + h * 16 + a_r) * LDA + a_c]);
        b_addr[h] = sptr(&Bs[(wn + h * 16 + b_r) * LDA + b_c]);
    }

    float acc[4][8][4];
#pragma unroll
    for (int i = 0; i < 4; i++)
#pragma unroll
        for (int j = 0; j < 8; j++)
#pragma unroll
            for (int e = 0; e < 4; e++) acc[i][j][e] = 0.0f;

    float4 ra0, ra1, rb[4];
    ra0 = *(const float4*)(Qb + (size_t)(m0 + arow) * DDIM + ach);
    ra1 = *(const float4*)(Qb + (size_t)(m0 + arow + 64) * DDIM + ach);
#pragma unroll
    for (int i = 0; i < 4; i++) {
        int idx = tid + i * 256, row = idx >> 2, ch = (idx & 3) * 4;
        rb[i] = *(const float4*)(Kb + (size_t)(n0 + row) * DDIM + ch);
    }
    *(float4*)&As[arow * LDA + ach]        = to_tf32_4(ra0);
    *(float4*)&As[(arow + 64) * LDA + ach] = to_tf32_4(ra1);
#pragma unroll
    for (int i = 0; i < 4; i++) {
        int idx = tid + i * 256, row = idx >> 2, ch = (idx & 3) * 4;
        *(float4*)&Bs[row * LDA + ch] = to_tf32_4(rb[i]);
    }
    __syncthreads();

    const int nt = DDIM / BK;   // 64
    for (int it = 0; it < nt; ++it) {
        const int s = it & 1;
        const uint32_t sa = s * (A_FL * 4), sb2 = s * (B_FL * 4);
        if (it + 1 < nt) {
            const int d0 = (it + 1) * BK;
            ra0 = *(const float4*)(Qb + (size_t)(m0 + arow) * DDIM + d0 + ach);
            ra1 = *(const float4*)(Qb + (size_t)(m0 + arow + 64) * DDIM + d0 + ach);
#pragma unroll
            for (int i = 0; i < 4; i++) {
                int idx = tid + i * 256, row = idx >> 2, ch = (idx & 3) * 4;
                rb[i] = *(const float4*)(Kb + (size_t)(n0 + row) * DDIM + d0 + ch);
            }
        }

#pragma unroll
        for (int kk = 0; kk < 2; ++kk) {
            uint32_t af[4][4], bf[4][4];
#pragma unroll
            for (int h = 0; h < 4; h++) ldsm4(af[h], a_addr[h] + sa + kk * 32);
#pragma unroll
            for (int h = 0; h < 4; h++) ldsm4(bf[h], b_addr[h] + sb2 + kk * 32);
#pragma unroll
            for (int mi = 0; mi < 4; mi++)
#pragma unroll
                for (int ni = 0; ni < 8; ni++)
                    mma8(acc[mi][ni], af[mi],
                         bf[ni >> 1][(ni & 1) * 2], bf[ni >> 1][(ni & 1) * 2 + 1]);
        }

        if (it + 1 < nt) {
            float* As1 = As + (s ^ 1) * A_FL;
            float* Bs1 = Bs + (s ^ 1) * B_FL;
            *(float4*)&As1[arow * LDA + ach]        = to_tf32_4(ra0);
            *(float4*)&As1[(arow + 64) * LDA + ach] = to_tf32_4(ra1);
#pragma unroll
            for (int i = 0; i < 4; i++) {
                int idx = tid + i * 256, row = idx >> 2, ch = (idx & 3) * 4;
                *(float4*)&Bs1[row * LDA + ch] = to_tf32_4(rb[i]);
            }
            __syncthreads();
        }
    }

    const int g = lane >> 2, t2 = (lane & 3) * 2;
#pragma unroll
    for (int mi = 0; mi < 4; mi++)
#pragma unroll
        for (int ni = 0; ni < 8; ni++) {
            float* p = Sb + (size_t)(m0 + wm + mi * 16 + g) * LSEQ + (n0 + wn + ni * 8 + t2);
            *(float2*)p = make_float2(acc[mi][ni][0], acc[mi][ni][1]);
            *(float2*)(p + (size_t)8 * LSEQ) = make_float2(acc[mi][ni][2], acc[mi][ni][3]);
        }
}

// ---------------------------------------------------------------------------
// Kernel 2: row softmax of S/32 with causal mask; masked entries -> exact 0
// ---------------------------------------------------------------------------
__global__ __launch_bounds__(256) void softmax_kernel() {
    const int q = blockIdx.x;
    const int b = blockIdx.y;
    float* row = g_S + ((size_t)b * LSEQ + q) * LSEQ;
    const int tid = threadIdx.x;

    float v[8];
    float mx = -1e30f;
#pragma unroll
    for (int j = 0; j < 8; j++) {
        int i = tid + j * 256;
        float s = (i <= q) ? row[i] * (1.0f / 32.0f) : -1e30f;
        v[j] = s;
        mx = fmaxf(mx, s);
    }
    __shared__ float red[8];
#pragma unroll
    for (int o = 16; o > 0; o >>= 1) mx = fmaxf(mx, __shfl_xor_sync(0xFFFFFFFFu, mx, o));
    if ((tid & 31) == 0) red[tid >> 5] = mx;
    __syncthreads();
    float m = red[0];
#pragma unroll
    for (int w = 1; w < 8; w++) m = fmaxf(m, red[w]);
    __syncthreads();

    float sum = 0.0f;
#pragma unroll
    for (int j = 0; j < 8; j++) {
        float e = exp2f((v[j] - m) * 1.4426950408889634f);
        v[j] = e;
        sum += e;
    }
#pragma unroll
    for (int o = 16; o > 0; o >>= 1) sum += __shfl_xor_sync(0xFFFFFFFFu, sum, o);
    if ((tid & 31) == 0) red[tid >> 5] = sum;
    __syncthreads();
    float tot = 0.0f;
#pragma unroll
    for (int w = 0; w < 8; w++) tot += red[w];
    const float r = 1.0f / tot;
#pragma unroll
    for (int j = 0; j < 8; j++) row[tid + j * 256] = v[j] * r;
}

// ---------------------------------------------------------------------------
// Kernel 3: O = P @ V, 128x256 block, 64x64 warp tiles, causal K-trip
// ---------------------------------------------------------------------------
__global__ __launch_bounds__(256, 1) void pv_kernel(const float* __restrict__ V,
                                                    float* __restrict__ O) {
    const int n0 = blockIdx.x * BN;   // head dim (0..3)
    const int m0 = blockIdx.y * BM;
    const int b  = blockIdx.z;

    extern __shared__ float smf[];
    float* As = smf;                  // 2 stages of A_FL
    float* Vs = smf + 2 * A_FL;       // 2 stages of V_FL, layout [k][n]

    const float* Pb = g_S + (size_t)b * LSEQ * LSEQ;
    const float* Vb = V   + (size_t)b * LSEQ * DDIM;
    float*       Ob = O   + (size_t)b * LSEQ * DDIM;

    const int tid = threadIdx.x, lane = tid & 31, wid = tid >> 5;
    const int wm = (wid & 1) * 64, wn = (wid >> 1) * 64;

    const int arow = tid >> 2, ach = (tid & 3) * 4;
    const int vrow = tid >> 6, vch = (tid & 63) * 4;   // V: 4 rows per pass of 256 thr

    const int a_r = lane & 15, a_c = (lane & 16) >> 2;
    uint32_t a_addr[4];
#pragma unroll
    for (int h = 0; h < 4; h++)
        a_addr[h] = sptr(&As[(wm + h * 16 + a_r) * LDA + a_c]);

    const int bk = lane & 3, bn = lane >> 2;

    float acc[4][8][4];
#pragma unroll
    for (int i = 0; i < 4; i++)
#pragma unroll
        for (int j = 0; j < 8; j++)
#pragma unroll
            for (int e = 0; e < 4; e++) acc[i][j][e] = 0.0f;

    float4 ra0, ra1, rv[4];
    ra0 = *(const float4*)(Pb + (size_t)(m0 + arow) * LSEQ + ach);
    ra1 = *(const float4*)(Pb + (size_t)(m0 + arow + 64) * LSEQ + ach);
#pragma unroll
    for (int i = 0; i < 4; i++)
        rv[i] = *(const float4*)(Vb + (size_t)(vrow + i * 4) * DDIM + n0 + vch);
    *(float4*)&As[arow * LDA + ach]        = to_tf32_4(ra0);
    *(float4*)&As[(arow + 64) * LDA + ach] = to_tf32_4(ra1);
#pragma unroll
    for (int i = 0; i < 4; i++)
        *(float4*)&Vs[(vrow + i * 4) * LDV + vch] = to_tf32_4(rv[i]);
    __syncthreads();

    const int nt = (m0 + BM) / BK;    // P[q,k]==0 for k>q
    for (int it = 0; it < nt; ++it) {
        const int s = it & 1;
        const uint32_t sa = s * (A_FL * 4);
        float* Vsb = Vs + s * V_FL;
        if (it + 1 < nt) {
            const int k0 = (it + 1) * BK;
            ra0 = *(const float4*)(Pb + (size_t)(m0 + arow) * LSEQ + k0 + ach);
            ra1 = *(const float4*)(Pb + (size_t)(m0 + arow + 64) * LSEQ + k0 + ach);
#pragma unroll
            for (int i = 0; i < 4; i++)
                rv[i] = *(const float4*)(Vb + (size_t)(k0 + vrow + i * 4) * DDIM + n0 + vch);
        }

#pragma unroll
        for (int kk = 0; kk < 2; ++kk) {
            uint32_t af[4][4];
#pragma unroll
            for (int h = 0; h < 4; h++) ldsm4(af[h], a_addr[h] + sa + kk * 32);
            const float* vs0 = &Vsb[(kk * 8 + bk) * LDV];
            const float* vs1 = vs0 + 4 * LDV;
#pragma unroll
            for (int ni = 0; ni < 8; ni++) {
                uint32_t b0 = __float_as_uint(vs0[wn + ni * 8 + bn]);
                uint32_t b1 = __float_as_uint(vs1[wn + ni * 8 + bn]);
#pragma unroll
                for (int mi = 0; mi < 4; mi++)
                    mma8(acc[mi][ni], af[mi], b0, b1);
            }
        }

        if (it + 1 < nt) {
            float* As1 = As + (s ^ 1) * A_FL;
            float* Vs1 = Vs + (s ^ 1) * V_FL;
            *(float4*)&As1[arow * LDA + ach]        = to_tf32_4(ra0);
            *(float4*)&As1[(arow + 64) * LDA + ach] = to_tf32_4(ra1);
#pragma unroll
            for (int i = 0; i < 4; i++)
                *(float4*)&Vs1[(vrow + i * 4) * LDV + vch] = to_tf32_4(rv[i]);
            __syncthreads();
        }
    }

    const int g = lane >> 2, t2 = (lane & 3) * 2;
#pragma unroll
    for (int mi = 0; mi < 4; mi++)
#pragma unroll
        for (int ni = 0; ni < 8; ni++) {
            float* p = Ob + (size_t)(m0 + wm + mi * 16 + g) * DDIM + (n0 + wn + ni * 8 + t2);
            *(float2*)p = make_float2(acc[mi][ni][0], acc[mi][ni][1]);
            *(float2*)(p + (size_t)8 * DDIM) = make_float2(acc[mi][ni][2], acc[mi][ni][3]);
        }
}

// ---------------------------------------------------------------------------
extern "C" void kernel_launch(void* const* d_in, const int* in_sizes, int n_in,
                              void* d_out, int out_size) {
    const float* Q = (const float*)d_in[0];
    const float* K = (const float*)d_in[1];
    const float* V = (const float*)d_in[2];
    float* O = (float*)d_out;

    cudaFuncSetAttribute(qk_kernel, cudaFuncAttributeMaxDynamicSharedMemorySize, QK_SMEM_BYTES);
    cudaFuncSetAttribute(pv_kernel, cudaFuncAttributeMaxDynamicSharedMemorySize, PV_SMEM_BYTES);

    dim3 gQK(LSEQ / BN, LSEQ / BM, NB);    // 8 x 16 x 16
    qk_kernel<<<gQK, 256, QK_SMEM_BYTES>>>(Q, K);

    dim3 gSM(LSEQ, NB);                    // 2048 x 16
    softmax_kernel<<<gSM, 256>>>();

    dim3 gPV(DDIM / BN, LSEQ / BM, NB);    // 4 x 16 x 16
    pv_kernel<<<gPV, 256, PV_SMEM_BYTES>>>(V, O);
}

// round 6
// speedup vs baseline: 1.6000x; 1.6000x over previous
#include <cuda_runtime.h>
#include <cstdint>

#define NB    16
#define LSEQ  2048
#define DDIM  1024

#define BM 128
#define BN 128
#define BK 16
#define LDA 20      // floats; conflict-free LDSM rows
#define LDV 136     // floats; 136%32==8 -> conflict-free scalar B LDS

#define A_FL (BM * LDA)          // 2560
#define B_FL (BN * LDA)          // 2560
#define V_FL (BK * LDV)          // 2176

// 256 MB scratch for scores/probs: S[b, q, k]
__device__ float g_S[(size_t)NB * LSEQ * LSEQ];

__device__ __forceinline__ float to_tf32(float x) {
    float r;
    asm("cvt.rna.tf32.f32 %0, %1;" : "=f"(r) : "f"(x));
    return r;
}
__device__ __forceinline__ float4 to_tf32_4(float4 v) {
    v.x = to_tf32(v.x); v.y = to_tf32(v.y); v.z = to_tf32(v.z); v.w = to_tf32(v.w);
    return v;
}
__device__ __forceinline__ uint32_t sptr(const void* p) {
    return (uint32_t)__cvta_generic_to_shared(p);
}
__device__ __forceinline__ void ldsm4(uint32_t r[4], uint32_t a) {
    asm volatile("ldmatrix.sync.aligned.m8n8.x4.shared.b16 {%0,%1,%2,%3}, [%4];"
                 : "=r"(r[0]), "=r"(r[1]), "=r"(r[2]), "=r"(r[3]) : "r"(a));
}
__device__ __forceinline__ void mma8(float c[4], const uint32_t a[4],
                                     uint32_t b0, uint32_t b1) {
    asm volatile("mma.sync.aligned.m16n8k8.row.col.f32.tf32.tf32.f32 "
                 "{%0,%1,%2,%3}, {%4,%5,%6,%7}, {%8,%9}, {%0,%1,%2,%3};"
                 : "+f"(c[0]), "+f"(c[1]), "+f"(c[2]), "+f"(c[3])
                 : "r"(a[0]), "r"(a[1]), "r"(a[2]), "r"(a[3]), "r"(b0), "r"(b1));
}

// ---------------------------------------------------------------------------
// Kernel 1: S = Q @ K^T, 128x128 block, 64x32 warp tiles, double-buffered
// ---------------------------------------------------------------------------
__global__ __launch_bounds__(256, 2) void qk_kernel(const float* __restrict__ Q,
                                                    const float* __restrict__ Kin) {
    const int n0 = blockIdx.x * BN;
    const int m0 = blockIdx.y * BM;
    const int b  = blockIdx.z;
    if (n0 > m0 + BM - 1) return;     // fully masked tile

    __shared__ float As[2][A_FL];
    __shared__ float Bs[2][B_FL];

    const float* Qb = Q   + (size_t)b * LSEQ * DDIM;
    const float* Kb = Kin + (size_t)b * LSEQ * DDIM;
    float*       Sb = g_S + (size_t)b * LSEQ * LSEQ;

    const int tid = threadIdx.x, lane = tid & 31, wid = tid >> 5;
    const int wm = (wid & 1) * 64;       // 2 warps along M
    const int wn = (wid >> 1) * 32;      // 4 warps along N

    const int grow = tid >> 2, gch = (tid & 3) * 4;

    const int a_r = lane & 15, a_c = (lane & 16) >> 2;
    const int b_r = (lane & 7) + ((lane & 16) >> 1), b_c = (lane & 8) >> 1;

    uint32_t a_addr[4], b_addr[2];
#pragma unroll
    for (int h = 0; h < 4; h++)
        a_addr[h] = sptr(&As[0][(wm + h * 16 + a_r) * LDA + a_c]);
#pragma unroll
    for (int h = 0; h < 2; h++)
        b_addr[h] = sptr(&Bs[0][(wn + h * 16 + b_r) * LDA + b_c]);

    float acc[4][4][4];
#pragma unroll
    for (int i = 0; i < 4; i++)
#pragma unroll
        for (int j = 0; j < 4; j++)
#pragma unroll
            for (int e = 0; e < 4; e++) acc[i][j][e] = 0.0f;

    float4 ra0, ra1, rb0, rb1;
    ra0 = *(const float4*)(Qb + (size_t)(m0 + grow) * DDIM + gch);
    ra1 = *(const float4*)(Qb + (size_t)(m0 + grow + 64) * DDIM + gch);
    rb0 = *(const float4*)(Kb + (size_t)(n0 + grow) * DDIM + gch);
    rb1 = *(const float4*)(Kb + (size_t)(n0 + grow + 64) * DDIM + gch);
    *(float4*)&As[0][grow * LDA + gch]        = to_tf32_4(ra0);
    *(float4*)&As[0][(grow + 64) * LDA + gch] = to_tf32_4(ra1);
    *(float4*)&Bs[0][grow * LDA + gch]        = to_tf32_4(rb0);
    *(float4*)&Bs[0][(grow + 64) * LDA + gch] = to_tf32_4(rb1);
    __syncthreads();

    const int nt = DDIM / BK;   // 64
    for (int it = 0; it < nt; ++it) {
        const int s = it & 1;
        const uint32_t soA = s * (A_FL * 4), soB = s * (B_FL * 4);
        if (it + 1 < nt) {
            const int d0 = (it + 1) * BK;
            ra0 = *(const float4*)(Qb + (size_t)(m0 + grow) * DDIM + d0 + gch);
            ra1 = *(const float4*)(Qb + (size_t)(m0 + grow + 64) * DDIM + d0 + gch);
            rb0 = *(const float4*)(Kb + (size_t)(n0 + grow) * DDIM + d0 + gch);
            rb1 = *(const float4*)(Kb + (size_t)(n0 + grow + 64) * DDIM + d0 + gch);
        }

#pragma unroll
        for (int kk = 0; kk < 2; ++kk) {
            uint32_t af[4][4], bf[2][4];
#pragma unroll
            for (int h = 0; h < 4; h++) ldsm4(af[h], a_addr[h] + soA + kk * 32);
#pragma unroll
            for (int h = 0; h < 2; h++) ldsm4(bf[h], b_addr[h] + soB + kk * 32);
#pragma unroll
            for (int mi = 0; mi < 4; mi++)
#pragma unroll
                for (int ni = 0; ni < 4; ni++)
                    mma8(acc[mi][ni], af[mi],
                         bf[ni >> 1][(ni & 1) * 2], bf[ni >> 1][(ni & 1) * 2 + 1]);
        }

        if (it + 1 < nt) {
            const int s1 = s ^ 1;
            *(float4*)&As[s1][grow * LDA + gch]        = to_tf32_4(ra0);
            *(float4*)&As[s1][(grow + 64) * LDA + gch] = to_tf32_4(ra1);
            *(float4*)&Bs[s1][grow * LDA + gch]        = to_tf32_4(rb0);
            *(float4*)&Bs[s1][(grow + 64) * LDA + gch] = to_tf32_4(rb1);
            __syncthreads();
        }
    }

    const int g = lane >> 2, t2 = (lane & 3) * 2;
#pragma unroll
    for (int mi = 0; mi < 4; mi++)
#pragma unroll
        for (int ni = 0; ni < 4; ni++) {
            float* p = Sb + (size_t)(m0 + wm + mi * 16 + g) * LSEQ + (n0 + wn + ni * 8 + t2);
            *(float2*)p = make_float2(acc[mi][ni][0], acc[mi][ni][1]);
            *(float2*)(p + (size_t)8 * LSEQ) = make_float2(acc[mi][ni][2], acc[mi][ni][3]);
        }
}

// ---------------------------------------------------------------------------
// Kernel 2: row softmax of S/32 with causal mask; masked entries -> exact 0
// ---------------------------------------------------------------------------
__global__ __launch_bounds__(256) void softmax_kernel() {
    const int q = blockIdx.x;
    const int b = blockIdx.y;
    float* row = g_S + ((size_t)b * LSEQ + q) * LSEQ;
    const int tid = threadIdx.x;

    float v[8];
    float mx = -1e30f;
#pragma unroll
    for (int j = 0; j < 8; j++) {
        int i = tid + j * 256;
        float s = (i <= q) ? row[i] * (1.0f / 32.0f) : -1e30f;
        v[j] = s;
        mx = fmaxf(mx, s);
    }
    __shared__ float red[8];
#pragma unroll
    for (int o = 16; o > 0; o >>= 1) mx = fmaxf(mx, __shfl_xor_sync(0xFFFFFFFFu, mx, o));
    if ((tid & 31) == 0) red[tid >> 5] = mx;
    __syncthreads();
    float m = red[0];
#pragma unroll
    for (int w = 1; w < 8; w++) m = fmaxf(m, red[w]);
    __syncthreads();

    float sum = 0.0f;
#pragma unroll
    for (int j = 0; j < 8; j++) {
        float e = exp2f((v[j] - m) * 1.4426950408889634f);
        v[j] = e;
        sum += e;
    }
#pragma unroll
    for (int o = 16; o > 0; o >>= 1) sum += __shfl_xor_sync(0xFFFFFFFFu, sum, o);
    if ((tid & 31) == 0) red[tid >> 5] = sum;
    __syncthreads();
    float tot = 0.0f;
#pragma unroll
    for (int w = 0; w < 8; w++) tot += red[w];
    const float r = 1.0f / tot;
#pragma unroll
    for (int j = 0; j < 8; j++) row[tid + j * 256] = v[j] * r;
}

// ---------------------------------------------------------------------------
// Kernel 3: O = P @ V, 128x128 block, 64x32 warp tiles, causal K-trip
// ---------------------------------------------------------------------------
__global__ __launch_bounds__(256, 2) void pv_kernel(const float* __restrict__ V,
                                                    float* __restrict__ O) {
    const int n0 = blockIdx.x * BN;   // head dim (0..7)
    const int m0 = blockIdx.y * BM;
    const int b  = blockIdx.z;

    __shared__ float As[2][A_FL];
    __shared__ float Vs[2][V_FL];     // [k][n]

    const float* Pb = g_S + (size_t)b * LSEQ * LSEQ;
    const float* Vb = V   + (size_t)b * LSEQ * DDIM;
    float*       Ob = O   + (size_t)b * LSEQ * DDIM;

    const int tid = threadIdx.x, lane = tid & 31, wid = tid >> 5;
    const int wm = (wid & 1) * 64;
    const int wn = (wid >> 1) * 32;

    const int grow = tid >> 2, gch = (tid & 3) * 4;       // P loads
    const int vrow = tid >> 5, vch = (tid & 31) * 4;      // V loads: 8 rows/pass

    const int a_r = lane & 15, a_c = (lane & 16) >> 2;
    uint32_t a_addr[4];
#pragma unroll
    for (int h = 0; h < 4; h++)
        a_addr[h] = sptr(&As[0][(wm + h * 16 + a_r) * LDA + a_c]);

    const int bk = lane & 3, bn = lane >> 2;

    float acc[4][4][4];
#pragma unroll
    for (int i = 0; i < 4; i++)
#pragma unroll
        for (int j = 0; j < 4; j++)
#pragma unroll
            for (int e = 0; e < 4; e++) acc[i][j][e] = 0.0f;

    float4 ra0, ra1, rv0, rv1;
    ra0 = *(const float4*)(Pb + (size_t)(m0 + grow) * LSEQ + gch);
    ra1 = *(const float4*)(Pb + (size_t)(m0 + grow + 64) * LSEQ + gch);
    rv0 = *(const float4*)(Vb + (size_t)vrow * DDIM + n0 + vch);
    rv1 = *(const float4*)(Vb + (size_t)(vrow + 8) * DDIM + n0 + vch);
    *(float4*)&As[0][grow * LDA + gch]        = to_tf32_4(ra0);
    *(float4*)&As[0][(grow + 64) * LDA + gch] = to_tf32_4(ra1);
    *(float4*)&Vs[0][vrow * LDV + vch]        = to_tf32_4(rv0);
    *(float4*)&Vs[0][(vrow + 8) * LDV + vch]  = to_tf32_4(rv1);
    __syncthreads();

    const int nt = (m0 + BM) / BK;    // P[q,k]==0 for k>q
    for (int it = 0; it < nt; ++it) {
        const int s = it & 1;
        const uint32_t soA = s * (A_FL * 4);
        const float* Vsb = Vs[s];
        if (it + 1 < nt) {
            const int k0 = (it + 1) * BK;
            ra0 = *(const float4*)(Pb + (size_t)(m0 + grow) * LSEQ + k0 + gch);
            ra1 = *(const float4*)(Pb + (size_t)(m0 + grow + 64) * LSEQ + k0 + gch);
            rv0 = *(const float4*)(Vb + (size_t)(k0 + vrow) * DDIM + n0 + vch);
            rv1 = *(const float4*)(Vb + (size_t)(k0 + vrow + 8) * DDIM + n0 + vch);
        }

#pragma unroll
        for (int kk = 0; kk < 2; ++kk) {
            uint32_t af[4][4];
#pragma unroll
            for (int h = 0; h < 4; h++) ldsm4(af[h], a_addr[h] + soA + kk * 32);
            const float* vs0 = &Vsb[(kk * 8 + bk) * LDV];
            const float* vs1 = vs0 + 4 * LDV;
#pragma unroll
            for (int ni = 0; ni < 4; ni++) {
                uint32_t b0 = __float_as_uint(vs0[wn + ni * 8 + bn]);
                uint32_t b1 = __float_as_uint(vs1[wn + ni * 8 + bn]);
#pragma unroll
                for (int mi = 0; mi < 4; mi++)
                    mma8(acc[mi][ni], af[mi], b0, b1);
            }
        }

        if (it + 1 < nt) {
            const int s1 = s ^ 1;
            *(float4*)&As[s1][grow * LDA + gch]        = to_tf32_4(ra0);
            *(float4*)&As[s1][(grow + 64) * LDA + gch] = to_tf32_4(ra1);
            *(float4*)&Vs[s1][vrow * LDV + vch]        = to_tf32_4(rv0);
            *(float4*)&Vs[s1][(vrow + 8) * LDV + vch]  = to_tf32_4(rv1);
            __syncthreads();
        }
    }

    const int g = lane >> 2, t2 = (lane & 3) * 2;
#pragma unroll
    for (int mi = 0; mi < 4; mi++)
#pragma unroll
        for (int ni = 0; ni < 4; ni++) {
            float* p = Ob + (size_t)(m0 + wm + mi * 16 + g) * DDIM + (n0 + wn + ni * 8 + t2);
            *(float2*)p = make_float2(acc[mi][ni][0], acc[mi][ni][1]);
            *(float2*)(p + (size_t)8 * DDIM) = make_float2(acc[mi][ni][2], acc[mi][ni][3]);
        }
}

// ---------------------------------------------------------------------------
extern "C" void kernel_launch(void* const* d_in, const int* in_sizes, int n_in,
                              void* d_out, int out_size) {
    const float* Q = (const float*)d_in[0];
    const float* K = (const float*)d_in[1];
    const float* V = (const float*)d_in[2];
    float* O = (float*)d_out;

    dim3 gQK(LSEQ / BN, LSEQ / BM, NB);    // 16 x 16 x 16
    qk_kernel<<<gQK, 256>>>(Q, K);

    dim3 gSM(LSEQ, NB);                    // 2048 x 16
    softmax_kernel<<<gSM, 256>>>();

    dim3 gPV(DDIM / BN, LSEQ / BM, NB);    // 8 x 16 x 16
    pv_kernel<<<gPV, 256>>>(V, O);
}

// round 7
// speedup vs baseline: 1.6096x; 1.0060x over previous
#include <cuda_runtime.h>
#include <cstdint>

#define NB    16
#define LSEQ  2048
#define DDIM  1024

#define BM 128
#define BN 128
#define BK 16
#define LDA 20      // floats; conflict-free LDSM rows (80B stride, 16B aligned)
#define LDV 136     // floats; 136%32==8 -> conflict-free scalar B LDS

#define A_FL (BM * LDA)          // 2560
#define B_FL (BN * LDA)          // 2560
#define V_FL (BK * LDV)          // 2176
#define NSTG 4
#define ST_QK ((A_FL + B_FL) * 4)   // 20480 B per stage
#define ST_PV ((A_FL + V_FL) * 4)   // 18944 B per stage
#define QK_SMEM (NSTG * ST_QK)      // 81920
#define PV_SMEM (NSTG * ST_PV)      // 75776

// 256 MB scratch for scores/probs: S[b, q, k]
__device__ float g_S[(size_t)NB * LSEQ * LSEQ];

__device__ __forceinline__ float to_tf32(float x) {
    float r;
    asm("cvt.rna.tf32.f32 %0, %1;" : "=f"(r) : "f"(x));
    return r;
}
__device__ __forceinline__ uint32_t rnd_u(uint32_t b) {
    return __float_as_uint(to_tf32(__uint_as_float(b)));
}
__device__ __forceinline__ uint32_t sptr(const void* p) {
    return (uint32_t)__cvta_generic_to_shared(p);
}
__device__ __forceinline__ void ldsm4(uint32_t r[4], uint32_t a) {
    asm volatile("ldmatrix.sync.aligned.m8n8.x4.shared.b16 {%0,%1,%2,%3}, [%4];"
                 : "=r"(r[0]), "=r"(r[1]), "=r"(r[2]), "=r"(r[3]) : "r"(a));
}
__device__ __forceinline__ void mma8(float c[4], const uint32_t a[4],
                                     uint32_t b0, uint32_t b1) {
    asm volatile("mma.sync.aligned.m16n8k8.row.col.f32.tf32.tf32.f32 "
                 "{%0,%1,%2,%3}, {%4,%5,%6,%7}, {%8,%9}, {%0,%1,%2,%3};"
                 : "+f"(c[0]), "+f"(c[1]), "+f"(c[2]), "+f"(c[3])
                 : "r"(a[0]), "r"(a[1]), "r"(a[2]), "r"(a[3]), "r"(b0), "r"(b1));
}
__device__ __forceinline__ void cp16(uint32_t s, const void* g) {
    asm volatile("cp.async.cg.shared.global [%0], [%1], 16;" :: "r"(s), "l"(g) : "memory");
}
__device__ __forceinline__ void cp_commit() {
    asm volatile("cp.async.commit_group;" ::: "memory");
}
__device__ __forceinline__ void cp_wait2() { asm volatile("cp.async.wait_group 2;" ::: "memory"); }
__device__ __forceinline__ void cp_wait1() { asm volatile("cp.async.wait_group 1;" ::: "memory"); }
__device__ __forceinline__ void cp_wait0() { asm volatile("cp.async.wait_group 0;" ::: "memory"); }

// ---------------------------------------------------------------------------
// Kernel 1: S = Q @ K^T, 128x128 block, 64x32 warp tiles, 4-stage cp.async
// ---------------------------------------------------------------------------
__global__ __launch_bounds__(256, 2) void qk_kernel(const float* __restrict__ Q,
                                                    const float* __restrict__ Kin) {
    const int n0 = blockIdx.x * BN;
    const int m0 = blockIdx.y * BM;
    const int b  = blockIdx.z;
    if (n0 > m0 + BM - 1) return;     // fully masked tile

    extern __shared__ char smem[];
    const uint32_t sb = sptr(smem);

    const float* Qb = Q   + (size_t)b * LSEQ * DDIM;
    const float* Kb = Kin + (size_t)b * LSEQ * DDIM;
    float*       Sb = g_S + (size_t)b * LSEQ * LSEQ;

    const int tid = threadIdx.x, lane = tid & 31, wid = tid >> 5;
    const int wm = (wid & 1) * 64;       // 2 warps along M
    const int wn = (wid >> 1) * 32;      // 4 warps along N

    const int grow = tid >> 2, gch = (tid & 3) * 4;
    const float* q0 = Qb + (size_t)(m0 + grow) * DDIM + gch;
    const float* q1 = Qb + (size_t)(m0 + grow + 64) * DDIM + gch;
    const float* k0p = Kb + (size_t)(n0 + grow) * DDIM + gch;
    const float* k1p = Kb + (size_t)(n0 + grow + 64) * DDIM + gch;
    const uint32_t dA0 = sb + (grow * LDA + gch) * 4;
    const uint32_t dA1 = sb + ((grow + 64) * LDA + gch) * 4;
    const uint32_t dB0 = sb + A_FL * 4 + (grow * LDA + gch) * 4;
    const uint32_t dB1 = sb + A_FL * 4 + ((grow + 64) * LDA + gch) * 4;

    const int a_r = lane & 15, a_c = (lane & 16) >> 2;
    const int b_r = (lane & 7) + ((lane & 16) >> 1), b_c = (lane & 8) >> 1;

    uint32_t a_addr[4], b_addr[2];
#pragma unroll
    for (int h = 0; h < 4; h++)
        a_addr[h] = sb + ((wm + h * 16 + a_r) * LDA + a_c) * 4;
#pragma unroll
    for (int h = 0; h < 2; h++)
        b_addr[h] = sb + A_FL * 4 + ((wn + h * 16 + b_r) * LDA + b_c) * 4;

    float acc[4][4][4];
#pragma unroll
    for (int i = 0; i < 4; i++)
#pragma unroll
        for (int j = 0; j < 4; j++)
#pragma unroll
            for (int e = 0; e < 4; e++) acc[i][j][e] = 0.0f;

    const int nt = DDIM / BK;   // 64
#pragma unroll
    for (int p = 0; p < NSTG - 1; p++) {           // prologue: stages 0..2
        const int d0 = p * BK;
        const uint32_t so = p * ST_QK;
        cp16(dA0 + so, q0 + d0);
        cp16(dA1 + so, q1 + d0);
        cp16(dB0 + so, k0p + d0);
        cp16(dB1 + so, k1p + d0);
        cp_commit();
    }

    for (int it = 0; it < nt; ++it) {
        if (it < nt - 2) cp_wait2();
        else if (it == nt - 2) cp_wait1();
        else cp_wait0();
        __syncthreads();

        if (it + 3 < nt) {
            const int d0 = (it + 3) * BK;
            const uint32_t so = ((it + 3) & 3) * ST_QK;
            cp16(dA0 + so, q0 + d0);
            cp16(dA1 + so, q1 + d0);
            cp16(dB0 + so, k0p + d0);
            cp16(dB1 + so, k1p + d0);
            cp_commit();
        }

        const uint32_t so = (it & 3) * ST_QK;
#pragma unroll
        for (int kk = 0; kk < 2; ++kk) {
            uint32_t af[4][4], bf[2][4];
#pragma unroll
            for (int h = 0; h < 4; h++) ldsm4(af[h], a_addr[h] + so + kk * 32);
#pragma unroll
            for (int h = 0; h < 2; h++) {
                ldsm4(bf[h], b_addr[h] + so + kk * 32);
                bf[h][0] = rnd_u(bf[h][0]); bf[h][1] = rnd_u(bf[h][1]);
                bf[h][2] = rnd_u(bf[h][2]); bf[h][3] = rnd_u(bf[h][3]);
            }
#pragma unroll
            for (int mi = 0; mi < 4; mi++)
#pragma unroll
                for (int ni = 0; ni < 4; ni++)
                    mma8(acc[mi][ni], af[mi],
                         bf[ni >> 1][(ni & 1) * 2], bf[ni >> 1][(ni & 1) * 2 + 1]);
        }
    }

    const int g = lane >> 2, t2 = (lane & 3) * 2;
#pragma unroll
    for (int mi = 0; mi < 4; mi++)
#pragma unroll
        for (int ni = 0; ni < 4; ni++) {
            float* p = Sb + (size_t)(m0 + wm + mi * 16 + g) * LSEQ + (n0 + wn + ni * 8 + t2);
            *(float2*)p = make_float2(acc[mi][ni][0], acc[mi][ni][1]);
            *(float2*)(p + (size_t)8 * LSEQ) = make_float2(acc[mi][ni][2], acc[mi][ni][3]);
        }
}

// ---------------------------------------------------------------------------
// Kernel 2: row softmax of S/32 with causal mask; writes tf32-rounded P
// ---------------------------------------------------------------------------
__global__ __launch_bounds__(256) void softmax_kernel() {
    const int q = blockIdx.x;
    const int b = blockIdx.y;
    float* row = g_S + ((size_t)b * LSEQ + q) * LSEQ;
    const int tid = threadIdx.x;

    float v[8];
    float mx = -1e30f;
#pragma unroll
    for (int j = 0; j < 8; j++) {
        int i = tid + j * 256;
        float s = (i <= q) ? row[i] * (1.0f / 32.0f) : -1e30f;
        v[j] = s;
        mx = fmaxf(mx, s);
    }
    __shared__ float red[8];
#pragma unroll
    for (int o = 16; o > 0; o >>= 1) mx = fmaxf(mx, __shfl_xor_sync(0xFFFFFFFFu, mx, o));
    if ((tid & 31) == 0) red[tid >> 5] = mx;
    __syncthreads();
    float m = red[0];
#pragma unroll
    for (int w = 1; w < 8; w++) m = fmaxf(m, red[w]);
    __syncthreads();

    float sum = 0.0f;
#pragma unroll
    for (int j = 0; j < 8; j++) {
        float e = exp2f((v[j] - m) * 1.4426950408889634f);
        v[j] = e;
        sum += e;
    }
#pragma unroll
    for (int o = 16; o > 0; o >>= 1) sum += __shfl_xor_sync(0xFFFFFFFFu, sum, o);
    if ((tid & 31) == 0) red[tid >> 5] = sum;
    __syncthreads();
    float tot = 0.0f;
#pragma unroll
    for (int w = 0; w < 8; w++) tot += red[w];
    const float r = 1.0f / tot;
#pragma unroll
    for (int j = 0; j < 8; j++) row[tid + j * 256] = to_tf32(v[j] * r);
}

// ---------------------------------------------------------------------------
// Kernel 3: O = P @ V, 128x128 block, 64x32 warp tiles, 4-stage cp.async
// ---------------------------------------------------------------------------
__global__ __launch_bounds__(256, 2) void pv_kernel(const float* __restrict__ V,
                                                    float* __restrict__ O) {
    const int n0 = blockIdx.x * BN;   // head dim (0..7)
    const int m0 = blockIdx.y * BM;
    const int b  = blockIdx.z;

    extern __shared__ float smf[];
    const uint32_t sb = sptr(smf);

    const float* Pb = g_S + (size_t)b * LSEQ * LSEQ;
    const float* Vb = V   + (size_t)b * LSEQ * DDIM;
    float*       Ob = O   + (size_t)b * LSEQ * DDIM;

    const int tid = threadIdx.x, lane = tid & 31, wid = tid >> 5;
    const int wm = (wid & 1) * 64;
    const int wn = (wid >> 1) * 32;

    const int grow = tid >> 2, gch = (tid & 3) * 4;
    const int vrow = tid >> 5, vch = (tid & 31) * 4;

    const float* p0 = Pb + (size_t)(m0 + grow) * LSEQ + gch;
    const float* p1 = Pb + (size_t)(m0 + grow + 64) * LSEQ + gch;
    const float* v0 = Vb + (size_t)vrow * DDIM + n0 + vch;
    const float* v1 = Vb + (size_t)(vrow + 8) * DDIM + n0 + vch;
    const uint32_t dA0 = sb + (grow * LDA + gch) * 4;
    const uint32_t dA1 = sb + ((grow + 64) * LDA + gch) * 4;
    const uint32_t dV0 = sb + A_FL * 4 + (vrow * LDV + vch) * 4;
    const uint32_t dV1 = sb + A_FL * 4 + ((vrow + 8) * LDV + vch) * 4;

    const int a_r = lane & 15, a_c = (lane & 16) >> 2;
    uint32_t a_addr[4];
#pragma unroll
    for (int h = 0; h < 4; h++)
        a_addr[h] = sb + ((wm + h * 16 + a_r) * LDA + a_c) * 4;

    const int bk = lane & 3, bn = lane >> 2;

    float acc[4][4][4];
#pragma unroll
    for (int i = 0; i < 4; i++)
#pragma unroll
        for (int j = 0; j < 4; j++)
#pragma unroll
            for (int e = 0; e < 4; e++) acc[i][j][e] = 0.0f;

    const int nt = (m0 + BM) / BK;    // 8..128; P[q,k]==0 for k>q
#pragma unroll
    for (int p = 0; p < NSTG - 1; p++) {
        const int k0 = p * BK;
        const uint32_t so = p * ST_PV;
        cp16(dA0 + so, p0 + k0);
        cp16(dA1 + so, p1 + k0);
        cp16(dV0 + so, v0 + (size_t)k0 * DDIM);
        cp16(dV1 + so, v1 + (size_t)k0 * DDIM);
        cp_commit();
    }

    for (int it = 0; it < nt; ++it) {
        if (it < nt - 2) cp_wait2();
        else if (it == nt - 2) cp_wait1();
        else cp_wait0();
        __syncthreads();

        if (it + 3 < nt) {
            const int k0 = (it + 3) * BK;
            const uint32_t so = ((it + 3) & 3) * ST_PV;
            cp16(dA0 + so, p0 + k0);
            cp16(dA1 + so, p1 + k0);
            cp16(dV0 + so, v0 + (size_t)k0 * DDIM);
            cp16(dV1 + so, v1 + (size_t)k0 * DDIM);
            cp_commit();
        }

        const uint32_t so = (it & 3) * ST_PV;
        const float* Vsb = smf + (A_FL + (it & 3) * (ST_PV / 4));
#pragma unroll
        for (int kk = 0; kk < 2; ++kk) {
            uint32_t af[4][4];
#pragma unroll
            for (int h = 0; h < 4; h++) ldsm4(af[h], a_addr[h] + so + kk * 32);
            const float* vs0 = &Vsb[(kk * 8 + bk) * LDV];
            const float* vs1 = vs0 + 4 * LDV;
#pragma unroll
            for (int ni = 0; ni < 4; ni++) {
                uint32_t b0 = __float_as_uint(to_tf32(vs0[wn + ni * 8 + bn]));
                uint32_t b1 = __float_as_uint(to_tf32(vs1[wn + ni * 8 + bn]));
#pragma unroll
                for (int mi = 0; mi < 4; mi++)
                    mma8(acc[mi][ni], af[mi], b0, b1);
            }
        }
    }

    const int g = lane >> 2, t2 = (lane & 3) * 2;
#pragma unroll
    for (int mi = 0; mi < 4; mi++)
#pragma unroll
        for (int ni = 0; ni < 4; ni++) {
            float* p = Ob + (size_t)(m0 + wm + mi * 16 + g) * DDIM + (n0 + wn + ni * 8 + t2);
            *(float2*)p = make_float2(acc[mi][ni][0], acc[mi][ni][1]);
            *(float2*)(p + (size_t)8 * DDIM) = make_float2(acc[mi][ni][2], acc[mi][ni][3]);
        }
}

// ---------------------------------------------------------------------------
extern "C" void kernel_launch(void* const* d_in, const int* in_sizes, int n_in,
                              void* d_out, int out_size) {
    const float* Q = (const float*)d_in[0];
    const float* K = (const float*)d_in[1];
    const float* V = (const float*)d_in[2];
    float* O = (float*)d_out;

    cudaFuncSetAttribute(qk_kernel, cudaFuncAttributeMaxDynamicSharedMemorySize, QK_SMEM);
    cudaFuncSetAttribute(pv_kernel, cudaFuncAttributeMaxDynamicSharedMemorySize, PV_SMEM);

    dim3 gQK(LSEQ / BN, LSEQ / BM, NB);    // 16 x 16 x 16
    qk_kernel<<<gQK, 256, QK_SMEM>>>(Q, K);

    dim3 gSM(LSEQ, NB);                    // 2048 x 16
    softmax_kernel<<<gSM, 256>>>();

    dim3 gPV(DDIM / BN, LSEQ / BM, NB);    // 8 x 16 x 16
    pv_kernel<<<gPV, 256, PV_SMEM>>>(V, O);
}

// round 8
// speedup vs baseline: 1.8292x; 1.1364x over previous
#include <cuda_runtime.h>
#include <cstdint>

#define NB    16
#define LSEQ  2048
#define DDIM  1024

#define BM 128
#define BN 128
#define BK 32
#define LDA 36      // floats; 144B row stride -> conflict-free LDSM (9r mod 32 distinct)
#define LDV 136     // floats; 136%32==8 -> conflict-free scalar B LDS

#define A_FL (BM * LDA)             // 4608 floats
#define V_FL (BK * LDV)             // 4352 floats
#define NSTG 3
#define ST_QK (2 * A_FL * 4)        // 36864 B per stage (A + B)
#define ST_PV ((A_FL + V_FL) * 4)   // 35840 B per stage
#define QK_SMEM (NSTG * ST_QK)      // 110592
#define PV_SMEM (NSTG * ST_PV)      // 107520

// 256 MB scratch for scores/probs: S[b, q, k]
__device__ float g_S[(size_t)NB * LSEQ * LSEQ];

__device__ __forceinline__ float to_tf32(float x) {
    float r;
    asm("cvt.rna.tf32.f32 %0, %1;" : "=f"(r) : "f"(x));
    return r;
}
__device__ __forceinline__ uint32_t rnd_u(uint32_t b) {
    return __float_as_uint(to_tf32(__uint_as_float(b)));
}
__device__ __forceinline__ uint32_t sptr(const void* p) {
    return (uint32_t)__cvta_generic_to_shared(p);
}
__device__ __forceinline__ void ldsm4(uint32_t r[4], uint32_t a) {
    asm volatile("ldmatrix.sync.aligned.m8n8.x4.shared.b16 {%0,%1,%2,%3}, [%4];"
                 : "=r"(r[0]), "=r"(r[1]), "=r"(r[2]), "=r"(r[3]) : "r"(a));
}
__device__ __forceinline__ void mma8(float c[4], const uint32_t a[4],
                                     uint32_t b0, uint32_t b1) {
    asm volatile("mma.sync.aligned.m16n8k8.row.col.f32.tf32.tf32.f32 "
                 "{%0,%1,%2,%3}, {%4,%5,%6,%7}, {%8,%9}, {%0,%1,%2,%3};"
                 : "+f"(c[0]), "+f"(c[1]), "+f"(c[2]), "+f"(c[3])
                 : "r"(a[0]), "r"(a[1]), "r"(a[2]), "r"(a[3]), "r"(b0), "r"(b1));
}
__device__ __forceinline__ void cp16(uint32_t s, const void* g) {
    asm volatile("cp.async.cg.shared.global [%0], [%1], 16;" :: "r"(s), "l"(g) : "memory");
}
__device__ __forceinline__ void cp_commit() {
    asm volatile("cp.async.commit_group;" ::: "memory");
}
__device__ __forceinline__ void cp_wait1() { asm volatile("cp.async.wait_group 1;" ::: "memory"); }
__device__ __forceinline__ void cp_wait0() { asm volatile("cp.async.wait_group 0;" ::: "memory"); }

// ---------------------------------------------------------------------------
// Kernel 1: S = Q @ K^T, 128x128 block, 64x32 warp tiles, BK=32, 3-stage
// ---------------------------------------------------------------------------
__global__ __launch_bounds__(256, 2) void qk_kernel(const float* __restrict__ Q,
                                                    const float* __restrict__ Kin) {
    const int n0 = blockIdx.x * BN;
    const int m0 = blockIdx.y * BM;
    const int b  = blockIdx.z;
    if (n0 > m0 + BM - 1) return;     // fully masked tile

    extern __shared__ char smem[];
    const uint32_t sb = sptr(smem);

    const float* Qb = Q   + (size_t)b * LSEQ * DDIM;
    const float* Kb = Kin + (size_t)b * LSEQ * DDIM;
    float*       Sb = g_S + (size_t)b * LSEQ * LSEQ;

    const int tid = threadIdx.x, lane = tid & 31, wid = tid >> 5;
    const int wm = (wid & 1) * 64;       // 2 warps along M
    const int wn = (wid >> 1) * 32;      // 4 warps along N

    // cp.async coords: 4 chunks each for A and B; row = tid>>3 + i*32, col chunk = (tid&7)*4
    const int crow = tid >> 3, cch = (tid & 7) * 4;
    const float* qsrc = Qb + (size_t)(m0 + crow) * DDIM + cch;
    const float* ksrc = Kb + (size_t)(n0 + crow) * DDIM + cch;
    const uint32_t dA = sb + (crow * LDA + cch) * 4;
    const uint32_t dB = sb + A_FL * 4 + (crow * LDA + cch) * 4;
    const uint32_t rstep = 32 * LDA * 4;          // 32 rows in smem
    const size_t   gstep = (size_t)32 * DDIM;     // 32 rows in gmem

    const int a_r = lane & 15, a_c = (lane & 16) >> 2;
    const int b_r = (lane & 7) + ((lane & 16) >> 1), b_c = (lane & 8) >> 1;

    uint32_t a_addr[4], b_addr[2];
#pragma unroll
    for (int h = 0; h < 4; h++)
        a_addr[h] = sb + ((wm + h * 16 + a_r) * LDA + a_c) * 4;
#pragma unroll
    for (int h = 0; h < 2; h++)
        b_addr[h] = sb + A_FL * 4 + ((wn + h * 16 + b_r) * LDA + b_c) * 4;

    float acc[4][4][4];
#pragma unroll
    for (int i = 0; i < 4; i++)
#pragma unroll
        for (int j = 0; j < 4; j++)
#pragma unroll
            for (int e = 0; e < 4; e++) acc[i][j][e] = 0.0f;

    const int nt = DDIM / BK;   // 32
#pragma unroll
    for (int p = 0; p < 2; p++) {                  // prologue: stages 0,1
        const int d0 = p * BK;
        const uint32_t so = p * ST_QK;
#pragma unroll
        for (int i = 0; i < 4; i++) {
            cp16(dA + so + i * rstep, qsrc + d0 + i * gstep);
            cp16(dB + so + i * rstep, ksrc + d0 + i * gstep);
        }
        cp_commit();
    }

    for (int it = 0; it < nt; ++it) {
        if (it == nt - 1) cp_wait0(); else cp_wait1();
        __syncthreads();

        if (it + 2 < nt) {
            const int d0 = (it + 2) * BK;
            const uint32_t so = ((it + 2) % 3) * ST_QK;
#pragma unroll
            for (int i = 0; i < 4; i++) {
                cp16(dA + so + i * rstep, qsrc + d0 + i * gstep);
                cp16(dB + so + i * rstep, ksrc + d0 + i * gstep);
            }
            cp_commit();
        }

        const uint32_t so = (it % 3) * ST_QK;
#pragma unroll
        for (int kk = 0; kk < 4; ++kk) {
            uint32_t af[4][4], bf[2][4];
#pragma unroll
            for (int h = 0; h < 4; h++) ldsm4(af[h], a_addr[h] + so + kk * 32);
#pragma unroll
            for (int h = 0; h < 2; h++) {
                ldsm4(bf[h], b_addr[h] + so + kk * 32);
                bf[h][0] = rnd_u(bf[h][0]); bf[h][1] = rnd_u(bf[h][1]);
                bf[h][2] = rnd_u(bf[h][2]); bf[h][3] = rnd_u(bf[h][3]);
            }
#pragma unroll
            for (int mi = 0; mi < 4; mi++)
#pragma unroll
                for (int ni = 0; ni < 4; ni++)
                    mma8(acc[mi][ni], af[mi],
                         bf[ni >> 1][(ni & 1) * 2], bf[ni >> 1][(ni & 1) * 2 + 1]);
        }
    }

    const int g = lane >> 2, t2 = (lane & 3) * 2;
#pragma unroll
    for (int mi = 0; mi < 4; mi++)
#pragma unroll
        for (int ni = 0; ni < 4; ni++) {
            float* p = Sb + (size_t)(m0 + wm + mi * 16 + g) * LSEQ + (n0 + wn + ni * 8 + t2);
            *(float2*)p = make_float2(acc[mi][ni][0], acc[mi][ni][1]);
            *(float2*)(p + (size_t)8 * LSEQ) = make_float2(acc[mi][ni][2], acc[mi][ni][3]);
        }
}

// ---------------------------------------------------------------------------
// Kernel 2: row softmax of S/32 with causal mask; writes tf32-rounded P
// ---------------------------------------------------------------------------
__global__ __launch_bounds__(256) void softmax_kernel() {
    const int q = blockIdx.x;
    const int b = blockIdx.y;
    float* row = g_S + ((size_t)b * LSEQ + q) * LSEQ;
    const int tid = threadIdx.x;

    float v[8];
    float mx = -1e30f;
#pragma unroll
    for (int j = 0; j < 8; j++) {
        int i = tid + j * 256;
        float s = -1e30f;
        if (i <= q) s = row[i] * (1.0f / 32.0f);
        v[j] = s;
        mx = fmaxf(mx, s);
    }
    __shared__ float red[8];
#pragma unroll
    for (int o = 16; o > 0; o >>= 1) mx = fmaxf(mx, __shfl_xor_sync(0xFFFFFFFFu, mx, o));
    if ((tid & 31) == 0) red[tid >> 5] = mx;
    __syncthreads();
    float m = red[0];
#pragma unroll
    for (int w = 1; w < 8; w++) m = fmaxf(m, red[w]);
    __syncthreads();

    float sum = 0.0f;
#pragma unroll
    for (int j = 0; j < 8; j++) {
        float e = exp2f((v[j] - m) * 1.4426950408889634f);
        v[j] = e;
        sum += e;
    }
#pragma unroll
    for (int o = 16; o > 0; o >>= 1) sum += __shfl_xor_sync(0xFFFFFFFFu, sum, o);
    if ((tid & 31) == 0) red[tid >> 5] = sum;
    __syncthreads();
    float tot = 0.0f;
#pragma unroll
    for (int w = 0; w < 8; w++) tot += red[w];
    const float r = 1.0f / tot;
#pragma unroll
    for (int j = 0; j < 8; j++) row[tid + j * 256] = to_tf32(v[j] * r);
}

// ---------------------------------------------------------------------------
// Kernel 3: O = P @ V, 128x128 block, 64x32 warp tiles, BK=32, 3-stage
// ---------------------------------------------------------------------------
__global__ __launch_bounds__(256, 2) void pv_kernel(const float* __restrict__ V,
                                                    float* __restrict__ O) {
    const int n0 = blockIdx.x * BN;   // head dim (0..7)
    const int m0 = blockIdx.y * BM;
    const int b  = blockIdx.z;

    extern __shared__ float smf[];
    const uint32_t sb = sptr(smf);

    const float* Pb = g_S + (size_t)b * LSEQ * LSEQ;
    const float* Vb = V   + (size_t)b * LSEQ * DDIM;
    float*       Ob = O   + (size_t)b * LSEQ * DDIM;

    const int tid = threadIdx.x, lane = tid & 31, wid = tid >> 5;
    const int wm = (wid & 1) * 64;
    const int wn = (wid >> 1) * 32;

    // A (P) coords: row = tid>>3 + i*32, chunk = (tid&7)*4
    const int crow = tid >> 3, cch = (tid & 7) * 4;
    const float* psrc = Pb + (size_t)(m0 + crow) * LSEQ + cch;
    const uint32_t dA = sb + (crow * LDA + cch) * 4;
    const uint32_t rstepA = 32 * LDA * 4;
    const size_t   gstepP = (size_t)32 * LSEQ;
    // V coords: row = tid>>5 + i*8, chunk = (tid&31)*4 (128 cols)
    const int vrow = tid >> 5, vch = (tid & 31) * 4;
    const float* vsrc = Vb + (size_t)vrow * DDIM + n0 + vch;
    const uint32_t dV = sb + A_FL * 4 + (vrow * LDV + vch) * 4;
    const uint32_t rstepV = 8 * LDV * 4;
    const size_t   gstepV = (size_t)8 * DDIM;

    const int a_r = lane & 15, a_c = (lane & 16) >> 2;
    uint32_t a_addr[4];
#pragma unroll
    for (int h = 0; h < 4; h++)
        a_addr[h] = sb + ((wm + h * 16 + a_r) * LDA + a_c) * 4;

    const int bk = lane & 3, bn = lane >> 2;

    float acc[4][4][4];
#pragma unroll
    for (int i = 0; i < 4; i++)
#pragma unroll
        for (int j = 0; j < 4; j++)
#pragma unroll
            for (int e = 0; e < 4; e++) acc[i][j][e] = 0.0f;

    const int nt = (m0 + BM) / BK;    // 4..64; P[q,k]==0 for k>q
#pragma unroll
    for (int p = 0; p < 2; p++) {
        const int k0 = p * BK;
        const uint32_t so = p * ST_PV;
#pragma unroll
        for (int i = 0; i < 4; i++) {
            cp16(dA + so + i * rstepA, psrc + k0 + i * gstepP);
            cp16(dV + so + i * rstepV, vsrc + (size_t)k0 * DDIM + i * gstepV);
        }
        cp_commit();
    }

    for (int it = 0; it < nt; ++it) {
        if (it == nt - 1) cp_wait0(); else cp_wait1();
        __syncthreads();

        if (it + 2 < nt) {
            const int k0 = (it + 2) * BK;
            const uint32_t so = ((it + 2) % 3) * ST_PV;
#pragma unroll
            for (int i = 0; i < 4; i++) {
                cp16(dA + so + i * rstepA, psrc + k0 + i * gstepP);
                cp16(dV + so + i * rstepV, vsrc + (size_t)k0 * DDIM + i * gstepV);
            }
            cp_commit();
        }

        const int st = it % 3;
        const uint32_t so = st * ST_PV;
        const float* Vsb = smf + A_FL + st * (ST_PV / 4);
#pragma unroll
        for (int kk = 0; kk < 4; ++kk) {
            uint32_t af[4][4];
#pragma unroll
            for (int h = 0; h < 4; h++) ldsm4(af[h], a_addr[h] + so + kk * 32);
            const float* vs0 = &Vsb[(kk * 8 + bk) * LDV];
            const float* vs1 = vs0 + 4 * LDV;
#pragma unroll
            for (int ni = 0; ni < 4; ni++) {
                uint32_t b0 = __float_as_uint(to_tf32(vs0[wn + ni * 8 + bn]));
                uint32_t b1 = __float_as_uint(to_tf32(vs1[wn + ni * 8 + bn]));
#pragma unroll
                for (int mi = 0; mi < 4; mi++)
                    mma8(acc[mi][ni], af[mi], b0, b1);
            }
        }
    }

    const int g = lane >> 2, t2 = (lane & 3) * 2;
#pragma unroll
    for (int mi = 0; mi < 4; mi++)
#pragma unroll
        for (int ni = 0; ni < 4; ni++) {
            float* p = Ob + (size_t)(m0 + wm + mi * 16 + g) * DDIM + (n0 + wn + ni * 8 + t2);
            *(float2*)p = make_float2(acc[mi][ni][0], acc[mi][ni][1]);
            *(float2*)(p + (size_t)8 * DDIM) = make_float2(acc[mi][ni][2], acc[mi][ni][3]);
        }
}

// ---------------------------------------------------------------------------
extern "C" void kernel_launch(void* const* d_in, const int* in_sizes, int n_in,
                              void* d_out, int out_size) {
    const float* Q = (const float*)d_in[0];
    const float* K = (const float*)d_in[1];
    const float* V = (const float*)d_in[2];
    float* O = (float*)d_out;

    cudaFuncSetAttribute(qk_kernel, cudaFuncAttributeMaxDynamicSharedMemorySize, QK_SMEM);
    cudaFuncSetAttribute(pv_kernel, cudaFuncAttributeMaxDynamicSharedMemorySize, PV_SMEM);

    dim3 gQK(LSEQ / BN, LSEQ / BM, NB);    // 16 x 16 x 16
    qk_kernel<<<gQK, 256, QK_SMEM>>>(Q, K);

    dim3 gSM(LSEQ, NB);                    // 2048 x 16
    softmax_kernel<<<gSM, 256>>>();

    dim3 gPV(DDIM / BN, LSEQ / BM, NB);    // 8 x 16 x 16
    pv_kernel<<<gPV, 256, PV_SMEM>>>(V, O);
}